// round 13
// baseline (speedup 1.0000x reference)
#include <cuda_runtime.h>
#include <cuda_bf16.h>
#include <stdint.h>

// GINGCN forward, bucket-CSR gather with bf16 message payload.
//   out[r] = (1+eps)*x[r] (fp32) + dis_r * sum rsqrt(deg[c]) * xb[c]  (bf16->fp32)
//
//   K0 prep: zero counters + dtype detect + convert x -> bf16 copy (g_xb)
//   K1 build: one edge pass; atomicAdd deg[col]; append col to bucket[row]
//   K2 gather: 1 warp/node (R7 shape: 256-thr blocks, unroll 4); lane owns 4
//      features; loads 8B bf16 per edge (256B/warp/edge = half the fp32 LTS
//      traffic; 25.6MB bf16 x fits fully in L2)
//   K3 drain overflow list with float atomics (no-op when empty)

#define N_MAX   100000
#define D       128
#define D4      (D / 4)        // 32 float4 per row
#define CAP     64
#define OVF_MAX 2000000

__device__ int   g_deg[N_MAX];                  // in-degree (col counts)
__device__ int   g_cnt[N_MAX];                  // per-row bucket fill counts
__device__ int   g_bkt[(size_t)N_MAX * CAP];    // bucket: col only
__device__ int   g_is64;                        // edge dtype flag
__device__ int   g_ovf_n;                       // overflow entry count
__device__ int2  g_ovf[OVF_MAX];                // overflow: {row, col}
__device__ uint2 g_xb[(size_t)N_MAX * D4];      // bf16 copy of x: 32 uint2/row

// ---------------------------------------------------------------- edge access
__device__ __forceinline__ int edge_val(const void* ei, size_t idx, int is64) {
    if (is64) return (int)((const long long*)ei)[idx];
    return ((const int*)ei)[idx];
}

// ---------------------------------------------------------------- K0: prep
// zero counters, detect edge dtype, convert x (fp32) -> g_xb (bf16 pairs).
__global__ void k_prep(const void* ei, const float4* __restrict__ x4,
                       int n, int n4) {
    int i = blockIdx.x * blockDim.x + threadIdx.x;
    if (i < n) { g_deg[i] = 0; g_cnt[i] = 0; }
    if (i == 0) {
        g_ovf_n = 0;
        const int* p = (const int*)ei;
        int nz = 0;
        #pragma unroll
        for (int k = 0; k < 64; k++) nz |= p[2 * k + 1];
        g_is64 = (nz == 0) ? 1 : 0;
    }
    if (i < n4) {
        float4 v = x4[i];
        __nv_bfloat162 lo = __floats2bfloat162_rn(v.x, v.y);
        __nv_bfloat162 hi = __floats2bfloat162_rn(v.z, v.w);
        uint2 u;
        u.x = *reinterpret_cast<unsigned*>(&lo);
        u.y = *reinterpret_cast<unsigned*>(&hi);
        g_xb[i] = u;
    }
}

// ---------------------------------------------------------------- K1: build
// Single pass: degree count and bucket append are independent, no deg reads.
__global__ void k_build(const void* ei, int E) {
    int e = blockIdx.x * blockDim.x + threadIdx.x;
    if (e >= E) return;
    int is64 = g_is64;
    int r = edge_val(ei, (size_t)e, is64);
    int c = edge_val(ei, (size_t)E + e, is64);
    atomicAdd(&g_deg[c], 1);
    int slot = atomicAdd(&g_cnt[r], 1);
    if (slot < CAP) {
        g_bkt[(size_t)r * CAP + slot] = c;
    } else {
        int o = atomicAdd(&g_ovf_n, 1);
        if (o < OVF_MAX) g_ovf[o] = make_int2(r, c);
    }
}

// ---------------------------------------------------------------- K2: gather
// out[w] = (1+eps)*x[w] + dis_w * sum rsqrt(deg[c]) * xb[c]
// deg[c] >= 1 guaranteed for bucketed edges (the edge itself counted).
__global__ void __launch_bounds__(256)
k_gather(const float4* __restrict__ x4, float4* __restrict__ o4,
         const float* __restrict__ eps, int n) {
    int w    = (blockIdx.x * blockDim.x + threadIdx.x) >> 5;
    int lane = threadIdx.x & 31;
    if (w >= n) return;

    int cnt = g_cnt[w];
    if (cnt > CAP) cnt = CAP;

    float  s  = 1.0f + eps[0];
    float4 xv = x4[(size_t)w * D4 + lane];       // fp32 self term (exact)
    float4 acc;
    acc.x = s * xv.x; acc.y = s * xv.y; acc.z = s * xv.z; acc.w = s * xv.w;

    int   dw    = g_deg[w];
    float dis_w = (dw > 0) ? rsqrtf((float)dw) : 0.0f;

    size_t base = (size_t)w * CAP;
    for (int j0 = 0; j0 < cnt; j0 += 32) {
        int   mycol = 0;
        float mynrm = 0.0f;
        int idx = j0 + lane;
        if (idx < cnt) {
            mycol = g_bkt[base + idx];
            mynrm = dis_w * rsqrtf((float)g_deg[mycol]);
        }
        int m = min(32, cnt - j0);

        #pragma unroll 4
        for (int j = 0; j < m; j++) {
            int   c  = __shfl_sync(0xffffffffu, mycol, j);
            float nm = __shfl_sync(0xffffffffu, mynrm, j);
            uint2 u  = g_xb[(size_t)c * D4 + lane];      // 8B bf16 payload
            __nv_bfloat162 lo = *reinterpret_cast<__nv_bfloat162*>(&u.x);
            __nv_bfloat162 hi = *reinterpret_cast<__nv_bfloat162*>(&u.y);
            float2 f0 = __bfloat1622float2(lo);
            float2 f1 = __bfloat1622float2(hi);
            acc.x += nm * f0.x;
            acc.y += nm * f0.y;
            acc.z += nm * f1.x;
            acc.w += nm * f1.y;
        }
    }
    o4[(size_t)w * D4 + lane] = acc;
}

// ---------------------------------------------------------------- K3: overflow
// Persistent drain of overflow list into out (no-op for this distribution).
__global__ void k_ovf(const float4* __restrict__ x4, float* out) {
    int nov = g_ovf_n;
    if (nov > OVF_MAX) nov = OVF_MAX;
    int warp  = (blockIdx.x * blockDim.x + threadIdx.x) >> 5;
    int nwarp = (gridDim.x * blockDim.x) >> 5;
    int lane  = threadIdx.x & 31;
    for (int i = warp; i < nov; i += nwarp) {
        int2 t = g_ovf[i];
        int dr = g_deg[t.x];
        int dc = g_deg[t.y];
        float nm = (dr > 0 && dc > 0) ? rsqrtf((float)dr * (float)dc) : 0.0f;
        float4 v = x4[(size_t)t.y * D4 + lane];
        float* o = out + (size_t)t.x * D + lane * 4;
        atomicAdd(o + 0, nm * v.x);
        atomicAdd(o + 1, nm * v.y);
        atomicAdd(o + 2, nm * v.z);
        atomicAdd(o + 3, nm * v.w);
    }
}

// ---------------------------------------------------------------- launch
extern "C" void kernel_launch(void* const* d_in, const int* in_sizes, int n_in,
                              void* d_out, int out_size) {
    const float* x   = (const float*)d_in[0];
    const float* eps = (const float*)d_in[1];
    const void*  ei  = d_in[2];
    float*       out = (float*)d_out;

    int n  = in_sizes[0] / D;      // 100000
    int E  = in_sizes[2] / 2;      // 1600000
    int n4 = n * D4;               // 3.2M float4 / uint2 elements

    const int T = 256;
    k_prep  <<<(n4 + T - 1) / T, T>>>(ei, (const float4*)x, n, n4);
    k_build <<<(E + T - 1) / T, T>>>(ei, E);
    k_gather<<<(n * 32 + T - 1) / T, T>>>((const float4*)x, (float4*)out, eps, n);
    k_ovf   <<<32, T>>>((const float4*)x, out);
}